// round 1
// baseline (speedup 1.0000x reference)
#include <cuda_runtime.h>
#include <cuda_bf16.h>
#include <cstdint>

#define NTOK 4096
#define NCH  64

// Scratch (static device globals; no dynamic allocation allowed)
__device__ float g_q[2][4][NCH][NTOK];   // 8 MB
__device__ float g_k[2][4][NCH][NTOK];   // 8 MB
__device__ float g_v[2][4][NCH][NTOK];   // 8 MB
__device__ float g_m[2][4][NTOK];
__device__ float g_z[2][4][NTOK];
__device__ float g_o[2][4][NCH][NTOK];   // 8 MB

// ---------------------------------------------------------------------------
// Kernel 1: 1x1 conv projection  out[b][o][n] = sum_c W[o][c] x[b][c][n] + bias[o]
// grid (8 n-splits, 4 batches), block 256
// ---------------------------------------------------------------------------
__global__ void proj_kernel(const float* __restrict__ x,
                            const float* __restrict__ W,
                            const float* __restrict__ bias,
                            int br, int which) {
    __shared__ float Wt[64][64];   // Wt[c][o]
    __shared__ float xs[64][64];   // xs[c][n_local]
    __shared__ float bs[64];

    int t = threadIdx.x;
    int b = blockIdx.y;
    int n0 = blockIdx.x * 512;

    float* out;
    if (which == 0)      out = &g_q[br][0][0][0];
    else if (which == 1) out = &g_k[br][0][0][0];
    else                 out = &g_v[br][0][0][0];
    out += (size_t)b * NCH * NTOK;

    for (int idx = t; idx < 64 * 64; idx += 256) {
        int o = idx >> 6, c = idx & 63;
        Wt[c][o] = W[idx];
    }
    if (t < 64) bs[t] = bias[t];
    __syncthreads();

    const float* xb = x + (size_t)b * NCH * NTOK;
    int tx = t & 15, ty = t >> 4;   // o = ty*4.., n = tx*4..

    for (int nc = 0; nc < 512; nc += 64) {
        __syncthreads();
        for (int idx = t; idx < 64 * 16; idx += 256) {
            int c = idx >> 4, n4 = idx & 15;
            *(float4*)&xs[c][n4 * 4] =
                *(const float4*)&xb[c * NTOK + n0 + nc + n4 * 4];
        }
        __syncthreads();

        float acc[4][4] = {};
        #pragma unroll 8
        for (int c = 0; c < 64; c++) {
            float wv[4], xv[4];
            *(float4*)wv = *(float4*)&Wt[c][ty * 4];
            *(float4*)xv = *(float4*)&xs[c][tx * 4];
            #pragma unroll
            for (int i = 0; i < 4; i++)
                #pragma unroll
                for (int j = 0; j < 4; j++)
                    acc[i][j] += wv[i] * xv[j];
        }
        #pragma unroll
        for (int i = 0; i < 4; i++) {
            int o = ty * 4 + i;
            float bb = bs[o];
            float4 r = make_float4(acc[i][0] + bb, acc[i][1] + bb,
                                   acc[i][2] + bb, acc[i][3] + bb);
            *(float4*)&out[o * NTOK + n0 + nc + tx * 4] = r;
        }
    }
}

// ---------------------------------------------------------------------------
// Kernel 2: per-row softmax stats (m, Z) via online max/sum over all j
// grid (32 i-tiles of 128, 2 branches, 4 batches), block 256
// dynamic smem: Qs[64][128] + Ks[64][128] = 64 KB
// ---------------------------------------------------------------------------
__global__ void rowstats_kernel() {
    extern __shared__ float sm[];
    float (*Qs)[128] = (float(*)[128])sm;
    float (*Ks)[128] = (float(*)[128])(sm + 64 * 128);

    int t = threadIdx.x;
    int i0 = blockIdx.x * 128;
    int br = blockIdx.y, b = blockIdx.z;

    const float* Qg = &g_q[br][b][0][0];
    const float* Kg = &g_k[br][b][0][0];

    for (int idx = t; idx < 64 * 32; idx += 256) {
        int c = idx >> 5, i4 = idx & 31;
        *(float4*)&Qs[c][i4 * 4] = *(const float4*)&Qg[c * NTOK + i0 + i4 * 4];
    }

    int tx = t & 15, ty = t >> 4;   // rows i = ty*8.., cols j = tx*8..
    float m_run[8], z_run[8];
    #pragma unroll
    for (int r = 0; r < 8; r++) { m_run[r] = -1e30f; z_run[r] = 0.f; }

    for (int jt = 0; jt < 32; jt++) {
        __syncthreads();
        for (int idx = t; idx < 64 * 32; idx += 256) {
            int c = idx >> 5, j4 = idx & 31;
            *(float4*)&Ks[c][j4 * 4] =
                *(const float4*)&Kg[c * NTOK + jt * 128 + j4 * 4];
        }
        __syncthreads();

        float acc[8][8] = {};
        #pragma unroll 8
        for (int c = 0; c < 64; c++) {
            float a[8], bv[8];
            *(float4*)a       = *(float4*)&Qs[c][ty * 8];
            *(float4*)(a + 4) = *(float4*)&Qs[c][ty * 8 + 4];
            *(float4*)bv       = *(float4*)&Ks[c][tx * 8];
            *(float4*)(bv + 4) = *(float4*)&Ks[c][tx * 8 + 4];
            #pragma unroll
            for (int r = 0; r < 8; r++)
                #pragma unroll
                for (int j = 0; j < 8; j++)
                    acc[r][j] += a[r] * bv[j];
        }

        #pragma unroll
        for (int r = 0; r < 8; r++) {
            float tm = acc[r][0];
            #pragma unroll
            for (int j = 1; j < 8; j++) tm = fmaxf(tm, acc[r][j]);
            #pragma unroll
            for (int s = 1; s < 16; s <<= 1)
                tm = fmaxf(tm, __shfl_xor_sync(0xffffffffu, tm, s));
            float mn = fmaxf(m_run[r], tm);
            float ps = 0.f;
            #pragma unroll
            for (int j = 0; j < 8; j++) ps += __expf(acc[r][j] - mn);
            #pragma unroll
            for (int s = 1; s < 16; s <<= 1)
                ps += __shfl_xor_sync(0xffffffffu, ps, s);
            z_run[r] = z_run[r] * __expf(m_run[r] - mn) + ps;
            m_run[r] = mn;
        }
    }

    if (tx == 0) {
        #pragma unroll
        for (int r = 0; r < 8; r++) {
            g_m[br][b][i0 + ty * 8 + r] = m_run[r];
            g_z[br][b][i0 + ty * 8 + r] = z_run[r];
        }
    }
}

// ---------------------------------------------------------------------------
// Kernel 3: out[c][j] = sum_i (v[c][i]/Z[i]) * exp(s[i][j]-m[i])
// grid (32 j-tiles of 128, 2 branches, 4 batches), block 256
// per i-tile (64): recompute S block, exp+normalize into Ps, then PV GEMM
// dynamic smem: Ks[64][128] + Qs[64][64] + Vs[64][64] + Ps[64][132] + m/z
// ---------------------------------------------------------------------------
__global__ void attn_pv_kernel() {
    extern __shared__ float sm[];
    float (*Ks)[128] = (float(*)[128])sm;                        // 8192
    float (*Qs)[64]  = (float(*)[64])(sm + 64 * 128);            // 4096
    float (*Vs)[64]  = (float(*)[64])(sm + 64 * 128 + 4096);     // 4096
    float (*Ps)[132] = (float(*)[132])(sm + 64 * 128 + 8192);    // 8448
    float* msm = sm + 64 * 128 + 8192 + 64 * 132;                // 64
    float* rzs = msm + 64;                                       // 64

    int t = threadIdx.x;
    int j0 = blockIdx.x * 128;
    int br = blockIdx.y, b = blockIdx.z;

    const float* Qg = &g_q[br][b][0][0];
    const float* Kg = &g_k[br][b][0][0];
    const float* Vg = &g_v[br][b][0][0];

    for (int idx = t; idx < 64 * 32; idx += 256) {
        int c = idx >> 5, j4 = idx & 31;
        *(float4*)&Ks[c][j4 * 4] = *(const float4*)&Kg[c * NTOK + j0 + j4 * 4];
    }

    int tx = t & 15, ty = t >> 4;   // S-block: rows i = ty*4.., cols j = tx*8..
    int u = t & 31,  w = t >> 5;    // GEMM: cols j = u*4.., rows c = w*8..

    float oacc[8][4] = {};

    for (int it = 0; it < 64; it++) {
        int i0 = it * 64;
        __syncthreads();
        for (int idx = t; idx < 64 * 16; idx += 256) {
            int c = idx >> 4, i4 = idx & 15;
            *(float4*)&Qs[c][i4 * 4] = *(const float4*)&Qg[c * NTOK + i0 + i4 * 4];
            *(float4*)&Vs[c][i4 * 4] = *(const float4*)&Vg[c * NTOK + i0 + i4 * 4];
        }
        if (t < 64) {
            msm[t] = g_m[br][b][i0 + t];
            rzs[t] = 1.0f / g_z[br][b][i0 + t];
        }
        __syncthreads();

        // S block [64 x 128]
        float sacc[4][8] = {};
        #pragma unroll 8
        for (int c = 0; c < 64; c++) {
            float a[4], bv[8];
            *(float4*)a        = *(float4*)&Qs[c][ty * 4];
            *(float4*)bv       = *(float4*)&Ks[c][tx * 8];
            *(float4*)(bv + 4) = *(float4*)&Ks[c][tx * 8 + 4];
            #pragma unroll
            for (int r = 0; r < 4; r++)
                #pragma unroll
                for (int j = 0; j < 8; j++)
                    sacc[r][j] += a[r] * bv[j];
        }
        #pragma unroll
        for (int r = 0; r < 4; r++) {
            int i = ty * 4 + r;
            float mm = msm[i], rz = rzs[i];
            #pragma unroll
            for (int j = 0; j < 8; j++)
                sacc[r][j] = __expf(sacc[r][j] - mm) * rz;
            *(float4*)&Ps[i][tx * 8]     = *(float4*)&sacc[r][0];
            *(float4*)&Ps[i][tx * 8 + 4] = *(float4*)&sacc[r][4];
        }
        __syncthreads();

        // PV GEMM: oacc[cc][jj] += Vs[w*8+cc][i] * Ps[i][u*4+jj]
        #pragma unroll 4
        for (int i = 0; i < 64; i++) {
            float p4[4];
            *(float4*)p4 = *(float4*)&Ps[i][u * 4];
            #pragma unroll
            for (int cc = 0; cc < 8; cc++) {
                float vv = Vs[w * 8 + cc][i];
                #pragma unroll
                for (int jj = 0; jj < 4; jj++)
                    oacc[cc][jj] += vv * p4[jj];
            }
        }
    }

    float* Og = &g_o[br][b][0][0];
    #pragma unroll
    for (int cc = 0; cc < 8; cc++)
        *(float4*)&Og[(w * 8 + cc) * NTOK + j0 + u * 4] = *(float4*)&oacc[cc][0];
}

// ---------------------------------------------------------------------------
// Kernel 4: y[b][o][n] = b_f[o] + sum_{c<64} Wf[o][c]*g1*Oh[c][n]
//                               + sum_{c<64} Wf[o][64+c]*g2*Ol[c][n]
// grid (8 n-splits, 4 batches), block 256, dynamic smem 64.25 KB
// ---------------------------------------------------------------------------
__global__ void final_kernel(const float* __restrict__ Wf,
                             const float* __restrict__ bf,
                             const float* __restrict__ g1p,
                             const float* __restrict__ g2p,
                             float* __restrict__ y) {
    extern __shared__ float sm[];
    float (*Wt)[64] = (float(*)[64])sm;              // [128][64]  Wt[c][o]
    float (*cs)[64] = (float(*)[64])(sm + 128 * 64); // [128][64]  cs[c][n]
    float* bs = sm + 2 * 128 * 64;

    int t = threadIdx.x;
    int b = blockIdx.y;
    int n0 = blockIdx.x * 512;
    float gg1 = *g1p, gg2 = *g2p;

    for (int idx = t; idx < 64 * 128; idx += 256) {
        int o = idx >> 7, c = idx & 127;
        Wt[c][o] = Wf[idx];
    }
    if (t < 64) bs[t] = bf[t];
    __syncthreads();

    int tx = t & 15, ty = t >> 4;
    for (int nc = 0; nc < 512; nc += 64) {
        __syncthreads();
        for (int idx = t; idx < 128 * 16; idx += 256) {
            int c = idx >> 4, n4 = idx & 15;
            const float* src = (c < 64) ? &g_o[0][b][c][0] : &g_o[1][b][c - 64][0];
            float g = (c < 64) ? gg1 : gg2;
            float4 v4 = *(const float4*)&src[n0 + nc + n4 * 4];
            v4.x *= g; v4.y *= g; v4.z *= g; v4.w *= g;
            *(float4*)&cs[c][n4 * 4] = v4;
        }
        __syncthreads();

        float acc[4][4] = {};
        #pragma unroll 8
        for (int c = 0; c < 128; c++) {
            float wv[4], xv[4];
            *(float4*)wv = *(float4*)&Wt[c][ty * 4];
            *(float4*)xv = *(float4*)&cs[c][tx * 4];
            #pragma unroll
            for (int i = 0; i < 4; i++)
                #pragma unroll
                for (int j = 0; j < 4; j++)
                    acc[i][j] += wv[i] * xv[j];
        }
        #pragma unroll
        for (int i = 0; i < 4; i++) {
            int o = ty * 4 + i;
            float bb = bs[o];
            float4 r = make_float4(acc[i][0] + bb, acc[i][1] + bb,
                                   acc[i][2] + bb, acc[i][3] + bb);
            *(float4*)&y[(size_t)b * NCH * NTOK + o * NTOK + n0 + nc + tx * 4] = r;
        }
    }
}

// ---------------------------------------------------------------------------
extern "C" void kernel_launch(void* const* d_in, const int* in_sizes, int n_in,
                              void* d_out, int out_size) {
    const float* x  = (const float*)d_in[0];
    // W/bias in order: qh,kh,vh, ql,kl,vl at indices (1,2),(3,4)...(11,12)
    const float* g1 = (const float*)d_in[13];
    const float* g2 = (const float*)d_in[14];
    const float* Wf = (const float*)d_in[15];
    const float* bf = (const float*)d_in[16];
    float* y = (float*)d_out;

    const int smem2 = 2 * 64 * 128 * 4;                              // 65536
    const int smem3 = (64 * 128 + 2 * 64 * 64 + 64 * 132 + 128) * 4; // 99840
    const int smem4 = (2 * 128 * 64 + 64) * 4;                       // 65792

    cudaFuncSetAttribute(rowstats_kernel, cudaFuncAttributeMaxDynamicSharedMemorySize, smem2);
    cudaFuncSetAttribute(attn_pv_kernel,  cudaFuncAttributeMaxDynamicSharedMemorySize, smem3);
    cudaFuncSetAttribute(final_kernel,    cudaFuncAttributeMaxDynamicSharedMemorySize, smem4);

    // 6 QKV projections
    for (int mi = 0; mi < 6; mi++) {
        const float* W = (const float*)d_in[1 + 2 * mi];
        const float* bb = (const float*)d_in[2 + 2 * mi];
        proj_kernel<<<dim3(8, 4), 256>>>(x, W, bb, mi / 3, mi % 3);
    }

    rowstats_kernel<<<dim3(32, 2, 4), 256, smem2>>>();
    attn_pv_kernel<<<dim3(32, 2, 4), 256, smem3>>>();
    final_kernel<<<dim3(8, 4), 256, smem4>>>(Wf, bf, g1, g2, y);
}